// round 14
// baseline (speedup 1.0000x reference)
#include <cuda_runtime.h>
#include <cuda_fp16.h>
#include <mma.h>

using namespace nvcuda;

#define T_ 4
#define B_ 32
#define C_ 384
#define N_ 256
#define HEADS_ 8
#define DH_ 48
#define MQK 768   // q rows [0,384) and k rows [384,768) stacked
#define K_ 384    // GEMM inner dim (both GEMMs)

static constexpr int BCN  = B_ * C_ * N_;        // 3,145,728
static constexpr int TBCN = T_ * BCN;            // 12,582,912

// ---------------- scratch (static device memory; no cudaMalloc allowed) ----
__device__ __half g_sT[TBCN];                         // spikes [z][n][c] (K2 B^T + repair)
__device__ __half g_qk[(size_t)T_ * B_ * MQK * N_];   // hi-only BN(conv(s)), fp16
__device__ __half g_y[TBCN];                          // attn*k, binary [z][c][n] (K4 B)
__device__ __half g_Wqk_hi[MQK * K_];
__device__ float  g_Wqk_f32[MQK * K_];                // exact folded weights (repair)
__device__ __half g_Wp_hi[C_ * K_];                   // proj: hi-only (~1.7e-4)
__device__ float  g_bias_qk[MQK];
__device__ float  g_bias_p[C_];

// ---------------- K0: fold BN into weights ---------------------------------
__global__ void prep_weights(
    const float* __restrict__ qw, const float* __restrict__ qg, const float* __restrict__ qb,
    const float* __restrict__ qm, const float* __restrict__ qv,
    const float* __restrict__ kw, const float* __restrict__ kg, const float* __restrict__ kb,
    const float* __restrict__ km, const float* __restrict__ kv,
    const float* __restrict__ pw, const float* __restrict__ pbias, const float* __restrict__ pg,
    const float* __restrict__ pbeta, const float* __restrict__ pm, const float* __restrict__ pv)
{
    int idx = blockIdx.x * blockDim.x + threadIdx.x;
    if (idx < MQK * K_) {
        int d = idx / K_, c = idx % K_;
        float w, inv;
        if (d < C_) {
            inv = qg[d] / sqrtf(qv[d] + 1e-5f);
            w = qw[d * C_ + c] * inv;
        } else {
            int dd = d - C_;
            inv = kg[dd] / sqrtf(kv[dd] + 1e-5f);
            w = kw[dd * C_ + c] * inv;
        }
        g_Wqk_hi[idx]  = __float2half(w);
        g_Wqk_f32[idx] = w;
    }
    if (idx < C_ * K_) {
        int d = idx / K_;
        float inv = pg[d] / sqrtf(pv[d] + 1e-5f);
        g_Wp_hi[idx] = __float2half(pw[idx] * inv);
    }
    if (idx < MQK) {
        float inv, bias;
        if (idx < C_) {
            inv = qg[idx] / sqrtf(qv[idx] + 1e-5f);
            bias = qb[idx] - qm[idx] * inv;
        } else {
            int d = idx - C_;
            inv = kg[d] / sqrtf(kv[d] + 1e-5f);
            bias = kb[d] - km[d] * inv;
        }
        g_bias_qk[idx] = bias;
    }
    if (idx < C_) {
        float inv = pg[idx] / sqrtf(pv[idx] + 1e-5f);
        g_bias_p[idx] = pbias[idx] * inv + pbeta[idx] - pm[idx] * inv;
    }
}

// ---------------- K1: LIF over time -> spikes, [z][n][c] only ---------------
__global__ __launch_bounds__(256) void lif_inputT(
    const float* __restrict__ x, __half* __restrict__ sT)
{
    __shared__ __half tile[T_][32][33];
    const int n0 = blockIdx.x * 32;
    const int c0 = blockIdx.y * 32;
    const int b  = blockIdx.z;
    const int tid = threadIdx.x;
    const int nl = tid & 31;
    const int cq = tid >> 5;

#pragma unroll
    for (int j = 0; j < 4; ++j) {
        const int cl = cq + j * 8;
        const int c  = c0 + cl;
        float v = 0.f;
#pragma unroll
        for (int t = 0; t < T_; ++t) {
            v = 0.5f * v + x[((size_t)(t * B_ + b) * C_ + c) * N_ + n0 + nl];
            if (v >= 1.0f) { tile[t][cl][nl] = __float2half(1.0f); v = 0.f; }
            else           { tile[t][cl][nl] = __float2half(0.0f); }
        }
    }
    __syncthreads();

    const int r2 = tid >> 3;           // n 0..31
    const int q4 = (tid & 7) * 4;      // c by 4
#pragma unroll
    for (int t = 0; t < T_; ++t) {
        __half hv[4];
#pragma unroll
        for (int i = 0; i < 4; ++i) hv[i] = tile[t][q4 + i][r2];
        *(uint2*)(sT + ((size_t)(t * B_ + b) * N_ + n0 + r2) * C_ + c0 + q4) = *(uint2*)hv;
    }
}

// ---------------- K2/K4: pipelined wmma GEMM (hi-only, m32n8k16, BK=64) ----
// Out[z] = A_hi @ B[z] + bias. BCOL: B read from sT [z][n][c] (B^T) with
// col-major fragments; else row-major [z][c][n]. 2-stage cp.async ring.
// BK=64 halves the barrier count (6 iters of 2048 MMA-cycles each).
#define BM 128
#define BN 128
#define BK 64
#define NIT (K_ / BK)         // 6
#define SA_STRIDE (BK + 8)    // 72 halfs
#define SB_STRIDE (BN + 8)    // 136 halfs (row-major B tile: 64 x 136)
#define SBT_STRIDE (BK + 8)   // 72 halfs (col-major B tile: 128 x 72)
#define GEMM_SMEM 73728

__device__ __forceinline__ void cp_async16(__half* smem_dst, const __half* gmem_src)
{
    unsigned saddr = (unsigned)__cvta_generic_to_shared(smem_dst);
    asm volatile("cp.async.cg.shared.global [%0], [%1], 16;\n" :: "r"(saddr), "l"(gmem_src));
}

template<bool HOUT, bool BCOL>
__global__ __launch_bounds__(256) void gemm_hi(
    const __half* __restrict__ A_hi,
    const __half* __restrict__ Bmat,
    const float* __restrict__ bias,
    void* __restrict__ OutV,
    int M)
{
    extern __shared__ char smem[];
    constexpr int SB_HALFS    = BCOL ? BM * SBT_STRIDE : BK * SB_STRIDE;
    constexpr int STAGE_HALFS = BM * SA_STRIDE + SB_HALFS;
    float* stage = (float*)smem;     // epilogue reuse (32 KB; buffers dead then)

    const int z     = blockIdx.z;
    const int tileM = blockIdx.y * BM;
    const int tileN = blockIdx.x * BN;
    const __half* Bz = Bmat + (size_t)z * K_ * N_;

    const int tid  = threadIdx.x;
    const int warp = tid >> 5;
    const int wm   = warp & 1;    // 2 warps along M (64 rows each)
    const int wn   = warp >> 1;   // 4 warps along N (32 cols each)

    wmma::fragment<wmma::accumulator, 32, 8, 16, float> c[2][4];
#pragma unroll
    for (int i = 0; i < 2; i++)
#pragma unroll
        for (int j = 0; j < 4; j++) wmma::fill_fragment(c[i][j], 0.0f);

    auto load_stage = [&](int it, int s) {
        const int k0 = it * BK;
        __half* dA = (__half*)smem + s * STAGE_HALFS;
        __half* dB = dA + BM * SA_STRIDE;
        // A tile 128x64 halfs = 1024 uint4 -> 4/thread
#pragma unroll
        for (int i = 0; i < 4; i++) {
            int v  = tid + i * 256;
            int r  = v >> 3;              // 0..127
            int ck = (v & 7) << 3;        // k by 8
            cp_async16(dA + r * SA_STRIDE + ck,
                       A_hi + (size_t)(tileM + r) * K_ + k0 + ck);
        }
        if (BCOL) {
            // B^T tile: 128 n-rows x 64 k halfs = 1024 uint4 -> 4/thread
#pragma unroll
            for (int i = 0; i < 4; i++) {
                int v  = tid + i * 256;
                int r  = v >> 3;          // n 0..127
                int ck = (v & 7) << 3;    // k by 8
                cp_async16(dB + r * SBT_STRIDE + ck,
                           Bz + (size_t)(tileN + r) * K_ + k0 + ck);
            }
        } else {
            // B tile: 64 k-rows x 128 n halfs = 1024 uint4 -> 4/thread
#pragma unroll
            for (int i = 0; i < 4; i++) {
                int v  = tid + i * 256;
                int r  = v >> 4;          // k 0..63
                int cn = (v & 15) << 3;   // n by 8
                cp_async16(dB + r * SB_STRIDE + cn,
                           Bz + (size_t)(k0 + r) * N_ + tileN + cn);
            }
        }
        asm volatile("cp.async.commit_group;");
    };

    load_stage(0, 0);

#pragma unroll
    for (int it = 0; it < NIT; ++it) {
        if (it + 1 < NIT) {
            load_stage(it + 1, (it + 1) & 1);
            asm volatile("cp.async.wait_group 1;");
        } else {
            asm volatile("cp.async.wait_group 0;");
        }
        __syncthreads();

        const __half* cA = (const __half*)smem + (it & 1) * STAGE_HALFS;
        const __half* cB = cA + BM * SA_STRIDE;

#pragma unroll
        for (int kk = 0; kk < BK / 16; ++kk) {
            wmma::fragment<wmma::matrix_a, 32, 8, 16, __half, wmma::row_major> afr[2];
#pragma unroll
            for (int i = 0; i < 2; i++)
                wmma::load_matrix_sync(afr[i], cA + (wm * 64 + i * 32) * SA_STRIDE + kk * 16, SA_STRIDE);
            if (BCOL) {
                wmma::fragment<wmma::matrix_b, 32, 8, 16, __half, wmma::col_major> bfr[4];
#pragma unroll
                for (int j = 0; j < 4; j++)
                    wmma::load_matrix_sync(bfr[j], cB + (wn * 32 + j * 8) * SBT_STRIDE + kk * 16, SBT_STRIDE);
#pragma unroll
                for (int i = 0; i < 2; i++)
#pragma unroll
                    for (int j = 0; j < 4; j++) wmma::mma_sync(c[i][j], afr[i], bfr[j], c[i][j]);
            } else {
                wmma::fragment<wmma::matrix_b, 32, 8, 16, __half, wmma::row_major> bfr[4];
#pragma unroll
                for (int j = 0; j < 4; j++)
                    wmma::load_matrix_sync(bfr[j], cB + kk * 16 * SB_STRIDE + wn * 32 + j * 8, SB_STRIDE);
#pragma unroll
                for (int i = 0; i < 2; i++)
#pragma unroll
                    for (int j = 0; j < 4; j++) wmma::mma_sync(c[i][j], afr[i], bfr[j], c[i][j]);
            }
        }
        __syncthreads();
    }

    // epilogue: two 64-row rounds through 32KB staging (+bias), coalesced
#pragma unroll
    for (int rnd = 0; rnd < 2; ++rnd) {
        if (wm == rnd) {
#pragma unroll
            for (int i = 0; i < 2; i++)
#pragma unroll
                for (int j = 0; j < 4; j++)
                    wmma::store_matrix_sync(stage + (i * 32) * BN + wn * 32 + j * 8,
                                            c[i][j], BN, wmma::mem_row_major);
        }
        __syncthreads();
#pragma unroll
        for (int q = 0; q < 8; ++q) {
            int v  = tid + q * 256;
            int m  = v >> 5;
            int n4 = (v & 31) << 2;
            float4 val = *(float4*)(stage + m * BN + n4);
            float bb = bias[tileM + rnd * 64 + m];
            size_t off = (size_t)z * M * N_ + (size_t)(tileM + rnd * 64 + m) * N_ + tileN + n4;
            if (HOUT) {
                __half h[4];
                h[0] = __float2half(val.x + bb);
                h[1] = __float2half(val.y + bb);
                h[2] = __float2half(val.z + bb);
                h[3] = __float2half(val.w + bb);
                *(uint2*)((__half*)OutV + off) = *(uint2*)h;
            } else {
                val.x += bb; val.y += bb; val.z += bb; val.w += bb;
                *(float4*)((float*)OutV + off) = val;
            }
        }
        __syncthreads();
    }
}

// ---------------- K3: spike attn (lean smem/regs) + exact repair ------------
// Same algorithm as R11/R13 (validated): half2 n-pairs, dynamic flag margin,
// warp-cooperative exact fp32 repair. Leaner: byte-packed t-counts in one u32
// per (g,n) (sums <=48 so byte adds cannot carry), list capped at 2048 with a
// correct inline scalar-repair fallback (observed cnt ~60, never triggers).
#define LISTCAP 2048

__device__ __forceinline__ unsigned repair_scalar(
    const __half* __restrict__ sT, const float* __restrict__ wrow, float bv,
    int b, int n)
{
    float v = 0.f; unsigned bits = 0;
#pragma unroll
    for (int t = 0; t < T_; ++t) {
        const __half* scol = sT + ((size_t)(t * B_ + b) * N_ + n) * C_;
        float part = 0.f;
        for (int cc = 0; cc < K_; ++cc)
            part += wrow[cc] * __half2float(scol[cc]);
        float val = part + bv;
        v = 0.5f * v + val;
        if (v >= 1.0f) { bits |= (1u << t); v = 0.f; }
    }
    return bits;
}

__global__ __launch_bounds__(256, 5) void spike_attn2(
    const __half* __restrict__ qk,
    const float* __restrict__ alpha_p,
    const __half* __restrict__ sT,
    const float* __restrict__ W32,
    const float* __restrict__ bias,
    __half* __restrict__ y)
{
    __shared__ unsigned char sBits[96][64];    // [0,48)=q chains, [48,96)=k  (6KB)
    __shared__ unsigned short list[LISTCAP];   // 4KB
    __shared__ unsigned int sSp[8][64];        // byte-packed t-counts (2KB)
    __shared__ int cnt;

    const int blk = blockIdx.x;
    const int n0  = (blk & 3) << 6;            // 4 chunks of 64 n
    const int hh  = (blk >> 2) & (HEADS_ - 1);
    const int b   = blk >> 5;
    const int tid  = threadIdx.x;
    const int g    = tid >> 5;
    const int lane = tid & 31;
    const int nA   = lane * 2;                 // local n pair
    const float alpha = *alpha_p;

    if (tid == 0) cnt = 0;
    __syncthreads();

    // ---- phase 1: approx chains (2 n per thread) + flags ----
    {
        const int n = n0 + nA;
#pragma unroll
        for (int d = 0; d < 6; ++d) {
            const int dh = g * 6 + d;
#pragma unroll
            for (int side = 0; side < 2; ++side) {
                const int row = side * C_ + hh * DH_ + dh;
                float vx = 0.f, vy = 0.f, ex = 0.f, ey = 0.f;
                unsigned bL = 0, bH = 0;
                bool fL = false, fH = false;
#pragma unroll
                for (int t = 0; t < T_; ++t) {
                    __half2 hv = *(const __half2*)(qk + ((size_t)(t * B_ + b) * MQK + row) * N_ + n);
                    float2 val = __half22float2(hv);
                    vx = 0.5f * vx + val.x;
                    ex = 0.5f * ex + 1.5e-3f + fabsf(val.x) * 6e-4f;
                    if (fabsf(vx - 1.0f) < ex) fL = true;
                    if (vx >= 1.0f) { bL |= (1u << t); vx = 0.f; ex = 0.f; }
                    vy = 0.5f * vy + val.y;
                    ey = 0.5f * ey + 1.5e-3f + fabsf(val.y) * 6e-4f;
                    if (fabsf(vy - 1.0f) < ey) fH = true;
                    if (vy >= 1.0f) { bH |= (1u << t); vy = 0.f; ey = 0.f; }
                }
                const int chain = side * 48 + dh;
                if (fL) {
                    int idx = atomicAdd(&cnt, 1);
                    if (idx < LISTCAP) list[idx] = (unsigned short)((chain << 6) | nA);
                    else bL = repair_scalar(sT, W32 + (size_t)row * K_, bias[row], b, n);
                }
                if (fH) {
                    int idx = atomicAdd(&cnt, 1);
                    if (idx < LISTCAP) list[idx] = (unsigned short)((chain << 6) | (nA + 1));
                    else bH = repair_scalar(sT, W32 + (size_t)row * K_, bias[row], b, n + 1);
                }
                sBits[chain][nA]     = (unsigned char)bL;
                sBits[chain][nA + 1] = (unsigned char)bH;
            }
        }
    }
    __syncthreads();

    // ---- phase 2: exact fp32 repair (one warp per flagged chain) ----
    {
        const int m = min(cnt, LISTCAP);
        for (int e = g; e < m; e += 8) {
            const int ent   = list[e];
            const int chain = ent >> 6;
            const int nloc  = ent & 63;
            const int row   = (chain < 48) ? (hh * DH_ + chain)
                                           : (C_ + hh * DH_ + (chain - 48));
            const int n = n0 + nloc;
            const float* wrow = W32 + (size_t)row * K_;
            float v = 0.f; unsigned bits = 0;
#pragma unroll
            for (int t = 0; t < T_; ++t) {
                const __half* scol = sT + ((size_t)(t * B_ + b) * N_ + n) * C_;
                float part = 0.f;
#pragma unroll
                for (int cix = 0; cix < K_ / 32; ++cix) {
                    int cc = lane + cix * 32;
                    part += wrow[cc] * __half2float(scol[cc]);
                }
#pragma unroll
                for (int o = 16; o; o >>= 1)
                    part += __shfl_xor_sync(0xFFFFFFFFu, part, o);
                float val = part + bias[row];
                v = 0.5f * v + val;
                if (v >= 1.0f) { bits |= (1u << t); v = 0.f; }
            }
            if (lane == 0) sBits[chain][nloc] = (unsigned char)bits;
        }
    }
    __syncthreads();

    // ---- phase 3: packed popcounts -> attn gate -> y (half2 stores) ----
    unsigned qpA = 0, qpB = 0, kpA = 0, kpB = 0;
#pragma unroll
    for (int d = 0; d < 6; ++d) {
        qpA |= (unsigned)sBits[g * 6 + d][nA]          << (4 * d);
        qpB |= (unsigned)sBits[g * 6 + d][nA + 1]      << (4 * d);
        kpA |= (unsigned)sBits[48 + g * 6 + d][nA]     << (4 * d);
        kpB |= (unsigned)sBits[48 + g * 6 + d][nA + 1] << (4 * d);
    }
    unsigned pkA = 0, pkB = 0;
#pragma unroll
    for (int t = 0; t < T_; ++t) {
        pkA |= (unsigned)__popc(qpA & (0x111111u << t)) << (8 * t);
        pkB |= (unsigned)__popc(qpB & (0x111111u << t)) << (8 * t);
    }
    sSp[g][nA]     = pkA;
    sSp[g][nA + 1] = pkB;
    __syncthreads();

    unsigned sumA = 0, sumB = 0;
#pragma unroll
    for (int gg = 0; gg < 8; ++gg) { sumA += sSp[gg][nA]; sumB += sSp[gg][nA + 1]; }

    float StA[T_], StB[T_];
#pragma unroll
    for (int t = 0; t < T_; ++t) {
        StA[t] = (float)((sumA >> (8 * t)) & 0xFFu);
        StB[t] = (float)((sumB >> (8 * t)) & 0xFFu);
    }

    const float om = 1.0f - alpha;
    float m2A = alpha * StA[0] + om * StA[1];
    float m2B = alpha * StB[0] + om * StB[1];
    float qsA[T_], qsB[T_];
    qsA[0] = StA[0] + StA[0];        qsB[0] = StB[0] + StB[0];
    qsA[1] = StA[0] + StA[1];        qsB[1] = StB[0] + StB[1];
    qsA[2] = m2A + StA[2];           qsB[2] = m2B + StB[2];
    qsA[3] = alpha * m2A + om * StA[2] + StA[3];
    qsB[3] = alpha * m2B + om * StB[2] + StB[3];

    const int rowq = hh * DH_ + g * 6;
    float vA = 0.f, vB = 0.f;
#pragma unroll
    for (int t = 0; t < T_; ++t) {
        vA = 0.5f * vA + qsA[t];
        vB = 0.5f * vB + qsB[t];
        bool fA = false, fB = false;
        if (vA >= 0.5f) { fA = true; vA = 0.f; }
        if (vB >= 0.5f) { fB = true; vB = 0.f; }
        size_t base = ((size_t)(t * B_ + b) * C_ + rowq) * N_ + n0 + nA;
#pragma unroll
        for (int d = 0; d < 6; ++d) {
            __half h2[2];
            h2[0] = (fA && ((kpA >> (4 * d + t)) & 1u)) ? __float2half(1.0f) : __float2half(0.0f);
            h2[1] = (fB && ((kpB >> (4 * d + t)) & 1u)) ? __float2half(1.0f) : __float2half(0.0f);
            *(uint*)(y + base + (size_t)d * N_) = *(uint*)h2;
        }
    }
}

// ---------------- launch ---------------------------------------------------
extern "C" void kernel_launch(void* const* d_in, const int* in_sizes, int n_in,
                              void* d_out, int out_size)
{
    (void)in_sizes; (void)n_in; (void)out_size;
    const float* x       = (const float*)d_in[0];
    const float* q_w     = (const float*)d_in[1];
    const float* q_gamma = (const float*)d_in[2];
    const float* q_beta  = (const float*)d_in[3];
    const float* q_mean  = (const float*)d_in[4];
    const float* q_var   = (const float*)d_in[5];
    const float* k_w     = (const float*)d_in[6];
    const float* k_gamma = (const float*)d_in[7];
    const float* k_beta  = (const float*)d_in[8];
    const float* k_mean  = (const float*)d_in[9];
    const float* k_var   = (const float*)d_in[10];
    const float* proj_w  = (const float*)d_in[11];
    const float* proj_b  = (const float*)d_in[12];
    const float* proj_g  = (const float*)d_in[13];
    const float* proj_be = (const float*)d_in[14];
    const float* proj_m  = (const float*)d_in[15];
    const float* proj_v  = (const float*)d_in[16];
    const float* m_alpha = (const float*)d_in[17];
    float* out = (float*)d_out;

    __half *sT_p, *y_p, *wqk_hi, *wp_hi, *qk_p;
    float *bias_qk, *bias_p, *w32_p;
    cudaGetSymbolAddress((void**)&sT_p,    g_sT);
    cudaGetSymbolAddress((void**)&y_p,     g_y);
    cudaGetSymbolAddress((void**)&wqk_hi,  g_Wqk_hi);
    cudaGetSymbolAddress((void**)&w32_p,   g_Wqk_f32);
    cudaGetSymbolAddress((void**)&wp_hi,   g_Wp_hi);
    cudaGetSymbolAddress((void**)&qk_p,    g_qk);
    cudaGetSymbolAddress((void**)&bias_qk, g_bias_qk);
    cudaGetSymbolAddress((void**)&bias_p,  g_bias_p);

    cudaFuncSetAttribute((gemm_hi<true, true>),   cudaFuncAttributeMaxDynamicSharedMemorySize, GEMM_SMEM);
    cudaFuncSetAttribute((gemm_hi<false, false>), cudaFuncAttributeMaxDynamicSharedMemorySize, GEMM_SMEM);

    // K0: weight prep (BN fold; q/k hi + exact fp32; proj hi-only)
    prep_weights<<<(MQK * K_) / 256, 256>>>(q_w, q_gamma, q_beta, q_mean, q_var,
                                            k_w, k_gamma, k_beta, k_mean, k_var,
                                            proj_w, proj_b, proj_g, proj_be, proj_m, proj_v);
    // K1: LIF(x) -> sT ([z][n][c] only)
    lif_inputT<<<dim3(N_ / 32, C_ / 32, B_), 256>>>(x, sT_p);
    // K2: qk = [Wq';Wk']_hi @ sT^T + bias (col-major B; fp16 out; BK=64 pipelined)
    gemm_hi<true, true><<<dim3(N_ / BN, MQK / BM, T_ * B_), 256, GEMM_SMEM>>>(
        wqk_hi, sT_p, bias_qk, qk_p, MQK);
    // K3: approx spikes + exact threshold repair + attn gate -> y
    spike_attn2<<<B_ * HEADS_ * (N_ / 64), 256>>>(qk_p, m_alpha, sT_p, w32_p, bias_qk, y_p);
    // K4: out = Wp'_hi @ y + bias_p (row-major B; fp32 out; BK=64 pipelined)
    gemm_hi<false, false><<<dim3(N_ / BN, C_ / BM, T_ * B_), 256, GEMM_SMEM>>>(
        wp_hi, y_p, bias_p, out, C_);
}

// round 15
// speedup vs baseline: 1.0722x; 1.0722x over previous
#include <cuda_runtime.h>
#include <cuda_fp16.h>
#include <mma.h>

using namespace nvcuda;

#define T_ 4
#define B_ 32
#define C_ 384
#define N_ 256
#define HEADS_ 8
#define DH_ 48
#define MQK 768   // q rows [0,384) and k rows [384,768) stacked
#define K_ 384    // GEMM inner dim (both GEMMs)

static constexpr int BCN  = B_ * C_ * N_;        // 3,145,728
static constexpr int TBCN = T_ * BCN;            // 12,582,912

// ---------------- scratch (static device memory; no cudaMalloc allowed) ----
__device__ __half g_sT[TBCN];                         // spikes [z][n][c] (K2 B^T + repair)
__device__ __half g_qk[(size_t)T_ * B_ * MQK * N_];   // hi-only BN(conv(s)), fp16
__device__ __half g_y[TBCN];                          // attn*k, binary [z][c][n] (K4 B)
__device__ __half g_Wqk_hi[MQK * K_];
__device__ float  g_Wqk_f32[MQK * K_];                // exact folded weights (repair)
__device__ __half g_Wp_hi[C_ * K_];                   // proj: hi-only (~1.7e-4)
__device__ float  g_bias_qk[MQK];
__device__ float  g_bias_p[C_];

// ---------------- K0: fold BN into weights ---------------------------------
__global__ void prep_weights(
    const float* __restrict__ qw, const float* __restrict__ qg, const float* __restrict__ qb,
    const float* __restrict__ qm, const float* __restrict__ qv,
    const float* __restrict__ kw, const float* __restrict__ kg, const float* __restrict__ kb,
    const float* __restrict__ km, const float* __restrict__ kv,
    const float* __restrict__ pw, const float* __restrict__ pbias, const float* __restrict__ pg,
    const float* __restrict__ pbeta, const float* __restrict__ pm, const float* __restrict__ pv)
{
    int idx = blockIdx.x * blockDim.x + threadIdx.x;
    if (idx < MQK * K_) {
        int d = idx / K_, c = idx % K_;
        float w, inv;
        if (d < C_) {
            inv = qg[d] / sqrtf(qv[d] + 1e-5f);
            w = qw[d * C_ + c] * inv;
        } else {
            int dd = d - C_;
            inv = kg[dd] / sqrtf(kv[dd] + 1e-5f);
            w = kw[dd * C_ + c] * inv;
        }
        g_Wqk_hi[idx]  = __float2half(w);
        g_Wqk_f32[idx] = w;
    }
    if (idx < C_ * K_) {
        int d = idx / K_;
        float inv = pg[d] / sqrtf(pv[d] + 1e-5f);
        g_Wp_hi[idx] = __float2half(pw[idx] * inv);
    }
    if (idx < MQK) {
        float inv, bias;
        if (idx < C_) {
            inv = qg[idx] / sqrtf(qv[idx] + 1e-5f);
            bias = qb[idx] - qm[idx] * inv;
        } else {
            int d = idx - C_;
            inv = kg[d] / sqrtf(kv[d] + 1e-5f);
            bias = kb[d] - km[d] * inv;
        }
        g_bias_qk[idx] = bias;
    }
    if (idx < C_) {
        float inv = pg[idx] / sqrtf(pv[idx] + 1e-5f);
        g_bias_p[idx] = pbias[idx] * inv + pbeta[idx] - pm[idx] * inv;
    }
}

// ---------------- K1: LIF over time -> spikes, [z][n][c] only ---------------
__global__ __launch_bounds__(256) void lif_inputT(
    const float* __restrict__ x, __half* __restrict__ sT)
{
    __shared__ __half tile[T_][32][33];
    const int n0 = blockIdx.x * 32;
    const int c0 = blockIdx.y * 32;
    const int b  = blockIdx.z;
    const int tid = threadIdx.x;
    const int nl = tid & 31;
    const int cq = tid >> 5;

#pragma unroll
    for (int j = 0; j < 4; ++j) {
        const int cl = cq + j * 8;
        const int c  = c0 + cl;
        float v = 0.f;
#pragma unroll
        for (int t = 0; t < T_; ++t) {
            v = 0.5f * v + x[((size_t)(t * B_ + b) * C_ + c) * N_ + n0 + nl];
            if (v >= 1.0f) { tile[t][cl][nl] = __float2half(1.0f); v = 0.f; }
            else           { tile[t][cl][nl] = __float2half(0.0f); }
        }
    }
    __syncthreads();

    const int r2 = tid >> 3;           // n 0..31
    const int q4 = (tid & 7) * 4;      // c by 4
#pragma unroll
    for (int t = 0; t < T_; ++t) {
        __half hv[4];
#pragma unroll
        for (int i = 0; i < 4; ++i) hv[i] = tile[t][q4 + i][r2];
        *(uint2*)(sT + ((size_t)(t * B_ + b) * N_ + n0 + r2) * C_ + c0 + q4) = *(uint2*)hv;
    }
}

// ---------------- K2/K4: pipelined wmma GEMM (hi-only, m32n8k16, BK=64) ----
// Out[z] = A_hi @ B[z] + bias. BCOL: B read from sT [z][n][c] (B^T) with
// col-major fragments; else row-major [z][c][n]. 2-stage cp.async ring.
// BK=64 halves the barrier count (6 iters of 2048 MMA-cycles each).
#define BM 128
#define BN 128
#define BK 64
#define NIT (K_ / BK)         // 6
#define SA_STRIDE (BK + 8)    // 72 halfs
#define SB_STRIDE (BN + 8)    // 136 halfs (row-major B tile: 64 x 136)
#define SBT_STRIDE (BK + 8)   // 72 halfs (col-major B tile: 128 x 72)
#define GEMM_SMEM 73728

__device__ __forceinline__ void cp_async16(__half* smem_dst, const __half* gmem_src)
{
    unsigned saddr = (unsigned)__cvta_generic_to_shared(smem_dst);
    asm volatile("cp.async.cg.shared.global [%0], [%1], 16;\n" :: "r"(saddr), "l"(gmem_src));
}

template<bool HOUT, bool BCOL>
__global__ __launch_bounds__(256) void gemm_hi(
    const __half* __restrict__ A_hi,
    const __half* __restrict__ Bmat,
    const float* __restrict__ bias,
    void* __restrict__ OutV,
    int M)
{
    extern __shared__ char smem[];
    constexpr int SB_HALFS    = BCOL ? BM * SBT_STRIDE : BK * SB_STRIDE;
    constexpr int STAGE_HALFS = BM * SA_STRIDE + SB_HALFS;
    float* stage = (float*)smem;     // epilogue reuse (32 KB; buffers dead then)

    const int z     = blockIdx.z;
    const int tileM = blockIdx.y * BM;
    const int tileN = blockIdx.x * BN;
    const __half* Bz = Bmat + (size_t)z * K_ * N_;

    const int tid  = threadIdx.x;
    const int warp = tid >> 5;
    const int wm   = warp & 1;    // 2 warps along M (64 rows each)
    const int wn   = warp >> 1;   // 4 warps along N (32 cols each)

    wmma::fragment<wmma::accumulator, 32, 8, 16, float> c[2][4];
#pragma unroll
    for (int i = 0; i < 2; i++)
#pragma unroll
        for (int j = 0; j < 4; j++) wmma::fill_fragment(c[i][j], 0.0f);

    auto load_stage = [&](int it, int s) {
        const int k0 = it * BK;
        __half* dA = (__half*)smem + s * STAGE_HALFS;
        __half* dB = dA + BM * SA_STRIDE;
        // A tile 128x64 halfs = 1024 uint4 -> 4/thread
#pragma unroll
        for (int i = 0; i < 4; i++) {
            int v  = tid + i * 256;
            int r  = v >> 3;              // 0..127
            int ck = (v & 7) << 3;        // k by 8
            cp_async16(dA + r * SA_STRIDE + ck,
                       A_hi + (size_t)(tileM + r) * K_ + k0 + ck);
        }
        if (BCOL) {
            // B^T tile: 128 n-rows x 64 k halfs = 1024 uint4 -> 4/thread
#pragma unroll
            for (int i = 0; i < 4; i++) {
                int v  = tid + i * 256;
                int r  = v >> 3;          // n 0..127
                int ck = (v & 7) << 3;    // k by 8
                cp_async16(dB + r * SBT_STRIDE + ck,
                           Bz + (size_t)(tileN + r) * K_ + k0 + ck);
            }
        } else {
            // B tile: 64 k-rows x 128 n halfs = 1024 uint4 -> 4/thread
#pragma unroll
            for (int i = 0; i < 4; i++) {
                int v  = tid + i * 256;
                int r  = v >> 4;          // k 0..63
                int cn = (v & 15) << 3;   // n by 8
                cp_async16(dB + r * SB_STRIDE + cn,
                           Bz + (size_t)(k0 + r) * N_ + tileN + cn);
            }
        }
        asm volatile("cp.async.commit_group;");
    };

    load_stage(0, 0);

#pragma unroll
    for (int it = 0; it < NIT; ++it) {
        if (it + 1 < NIT) {
            load_stage(it + 1, (it + 1) & 1);
            asm volatile("cp.async.wait_group 1;");
        } else {
            asm volatile("cp.async.wait_group 0;");
        }
        __syncthreads();

        const __half* cA = (const __half*)smem + (it & 1) * STAGE_HALFS;
        const __half* cB = cA + BM * SA_STRIDE;

#pragma unroll
        for (int kk = 0; kk < BK / 16; ++kk) {
            wmma::fragment<wmma::matrix_a, 32, 8, 16, __half, wmma::row_major> afr[2];
#pragma unroll
            for (int i = 0; i < 2; i++)
                wmma::load_matrix_sync(afr[i], cA + (wm * 64 + i * 32) * SA_STRIDE + kk * 16, SA_STRIDE);
            if (BCOL) {
                wmma::fragment<wmma::matrix_b, 32, 8, 16, __half, wmma::col_major> bfr[4];
#pragma unroll
                for (int j = 0; j < 4; j++)
                    wmma::load_matrix_sync(bfr[j], cB + (wn * 32 + j * 8) * SBT_STRIDE + kk * 16, SBT_STRIDE);
#pragma unroll
                for (int i = 0; i < 2; i++)
#pragma unroll
                    for (int j = 0; j < 4; j++) wmma::mma_sync(c[i][j], afr[i], bfr[j], c[i][j]);
            } else {
                wmma::fragment<wmma::matrix_b, 32, 8, 16, __half, wmma::row_major> bfr[4];
#pragma unroll
                for (int j = 0; j < 4; j++)
                    wmma::load_matrix_sync(bfr[j], cB + kk * 16 * SB_STRIDE + wn * 32 + j * 8, SB_STRIDE);
#pragma unroll
                for (int i = 0; i < 2; i++)
#pragma unroll
                    for (int j = 0; j < 4; j++) wmma::mma_sync(c[i][j], afr[i], bfr[j], c[i][j]);
            }
        }
        __syncthreads();
    }

    // epilogue: two 64-row rounds through 32KB staging (+bias), coalesced
#pragma unroll
    for (int rnd = 0; rnd < 2; ++rnd) {
        if (wm == rnd) {
#pragma unroll
            for (int i = 0; i < 2; i++)
#pragma unroll
                for (int j = 0; j < 4; j++)
                    wmma::store_matrix_sync(stage + (i * 32) * BN + wn * 32 + j * 8,
                                            c[i][j], BN, wmma::mem_row_major);
        }
        __syncthreads();
#pragma unroll
        for (int q = 0; q < 8; ++q) {
            int v  = tid + q * 256;
            int m  = v >> 5;
            int n4 = (v & 31) << 2;
            float4 val = *(float4*)(stage + m * BN + n4);
            float bb = bias[tileM + rnd * 64 + m];
            size_t off = (size_t)z * M * N_ + (size_t)(tileM + rnd * 64 + m) * N_ + tileN + n4;
            if (HOUT) {
                __half h[4];
                h[0] = __float2half(val.x + bb);
                h[1] = __float2half(val.y + bb);
                h[2] = __float2half(val.z + bb);
                h[3] = __float2half(val.w + bb);
                *(uint2*)((__half*)OutV + off) = *(uint2*)h;
            } else {
                val.x += bb; val.y += bb; val.z += bb; val.w += bb;
                *(float4*)((float*)OutV + off) = val;
            }
        }
        __syncthreads();
    }
}

// ---------------- K3: spike attn, half2 n-pairs + exact repair (R13) --------
// Block = (b, head, 64-n chunk); warp g owns dh group (6 ch) x 2 sides; each
// lane processes an n-pair via half2 (full 128B/warp loads). Dynamic flag
// margin e_t = 0.5 e + 1.5e-3 + |x|*6e-4 (resets on spike); flagged chains
// recomputed exactly in fp32. LISTCAP == total chains -> no overflow possible.
// NOTE (R14 lesson): no min-blocks launch bound, no byte-packing — this kernel
// is register-hungry; capping regs forces spills that cost more than occupancy.
#define LISTCAP 6144

__global__ __launch_bounds__(256) void spike_attn2(
    const __half* __restrict__ qk,
    const float* __restrict__ alpha_p,
    const __half* __restrict__ sT,
    const float* __restrict__ W32,
    const float* __restrict__ bias,
    __half* __restrict__ y)
{
    __shared__ unsigned char sBits[96][64];    // [0,48)=q chains, [48,96)=k
    __shared__ unsigned short list[LISTCAP];
    __shared__ int cnt;
    __shared__ float sS[8][T_][64];

    const int blk = blockIdx.x;
    const int n0  = (blk & 3) << 6;            // 4 chunks of 64 n
    const int hh  = (blk >> 2) & (HEADS_ - 1);
    const int b   = blk >> 5;
    const int tid  = threadIdx.x;
    const int g    = tid >> 5;
    const int lane = tid & 31;
    const int nA   = lane * 2;                 // local n pair
    const float alpha = *alpha_p;

    if (tid == 0) cnt = 0;
    __syncthreads();

    // ---- phase 1: approx chains (2 n per thread) + flags ----
    {
        const int n = n0 + nA;
#pragma unroll
        for (int d = 0; d < 6; ++d) {
            const int dh = g * 6 + d;
#pragma unroll
            for (int side = 0; side < 2; ++side) {
                const int row = side * C_ + hh * DH_ + dh;
                float vx = 0.f, vy = 0.f, ex = 0.f, ey = 0.f;
                unsigned bL = 0, bH = 0;
                bool fL = false, fH = false;
#pragma unroll
                for (int t = 0; t < T_; ++t) {
                    __half2 hv = *(const __half2*)(qk + ((size_t)(t * B_ + b) * MQK + row) * N_ + n);
                    float2 val = __half22float2(hv);
                    vx = 0.5f * vx + val.x;
                    ex = 0.5f * ex + 1.5e-3f + fabsf(val.x) * 6e-4f;
                    if (fabsf(vx - 1.0f) < ex) fL = true;
                    if (vx >= 1.0f) { bL |= (1u << t); vx = 0.f; ex = 0.f; }
                    vy = 0.5f * vy + val.y;
                    ey = 0.5f * ey + 1.5e-3f + fabsf(val.y) * 6e-4f;
                    if (fabsf(vy - 1.0f) < ey) fH = true;
                    if (vy >= 1.0f) { bH |= (1u << t); vy = 0.f; ey = 0.f; }
                }
                const int chain = side * 48 + dh;
                sBits[chain][nA]     = (unsigned char)bL;
                sBits[chain][nA + 1] = (unsigned char)bH;
                if (fL) list[atomicAdd(&cnt, 1)] = (unsigned short)((chain << 6) | nA);
                if (fH) list[atomicAdd(&cnt, 1)] = (unsigned short)((chain << 6) | (nA + 1));
            }
        }
    }
    __syncthreads();

    // ---- phase 2: exact fp32 repair (one warp per flagged chain) ----
    {
        const int m = cnt;
        for (int e = g; e < m; e += 8) {
            const int ent   = list[e];
            const int chain = ent >> 6;
            const int nloc  = ent & 63;
            const int row   = (chain < 48) ? (hh * DH_ + chain)
                                           : (C_ + hh * DH_ + (chain - 48));
            const int n = n0 + nloc;
            const float* wrow = W32 + (size_t)row * K_;
            float v = 0.f; unsigned bits = 0;
#pragma unroll
            for (int t = 0; t < T_; ++t) {
                const __half* scol = sT + ((size_t)(t * B_ + b) * N_ + n) * C_;
                float part = 0.f;
#pragma unroll
                for (int cix = 0; cix < K_ / 32; ++cix) {
                    int cc = lane + cix * 32;
                    part += wrow[cc] * __half2float(scol[cc]);
                }
#pragma unroll
                for (int o = 16; o; o >>= 1)
                    part += __shfl_xor_sync(0xFFFFFFFFu, part, o);
                float val = part + bias[row];
                v = 0.5f * v + val;
                if (v >= 1.0f) { bits |= (1u << t); v = 0.f; }
            }
            if (lane == 0) sBits[chain][nloc] = (unsigned char)bits;
        }
    }
    __syncthreads();

    // ---- phase 3: popcounts -> attn gate -> y (half2 stores) ----
    float SA[T_] = {0.f, 0.f, 0.f, 0.f};
    float SBv[T_] = {0.f, 0.f, 0.f, 0.f};
    unsigned kbA[6], kbB[6];
#pragma unroll
    for (int d = 0; d < 6; ++d) {
        unsigned qA = sBits[g * 6 + d][nA];
        unsigned qB = sBits[g * 6 + d][nA + 1];
        kbA[d] = sBits[48 + g * 6 + d][nA];
        kbB[d] = sBits[48 + g * 6 + d][nA + 1];
#pragma unroll
        for (int t = 0; t < T_; ++t) {
            SA[t]  += (float)((qA >> t) & 1u);
            SBv[t] += (float)((qB >> t) & 1u);
        }
    }
#pragma unroll
    for (int t = 0; t < T_; ++t) {
        sS[g][t][nA]     = SA[t];
        sS[g][t][nA + 1] = SBv[t];
    }
    __syncthreads();

    float StA[T_], StB[T_];
#pragma unroll
    for (int t = 0; t < T_; ++t) {
        float aA = 0.f, aB = 0.f;
#pragma unroll
        for (int gg = 0; gg < 8; ++gg) { aA += sS[gg][t][nA]; aB += sS[gg][t][nA + 1]; }
        StA[t] = aA; StB[t] = aB;
    }

    const float om = 1.0f - alpha;
    float m2A = alpha * StA[0] + om * StA[1];
    float m2B = alpha * StB[0] + om * StB[1];
    float qsA[T_], qsB[T_];
    qsA[0] = StA[0] + StA[0];        qsB[0] = StB[0] + StB[0];
    qsA[1] = StA[0] + StA[1];        qsB[1] = StB[0] + StB[1];
    qsA[2] = m2A + StA[2];           qsB[2] = m2B + StB[2];
    qsA[3] = alpha * m2A + om * StA[2] + StA[3];
    qsB[3] = alpha * m2B + om * StB[2] + StB[3];

    const int rowq = hh * DH_ + g * 6;
    float vA = 0.f, vB = 0.f;
#pragma unroll
    for (int t = 0; t < T_; ++t) {
        vA = 0.5f * vA + qsA[t];
        vB = 0.5f * vB + qsB[t];
        bool fA = false, fB = false;
        if (vA >= 0.5f) { fA = true; vA = 0.f; }
        if (vB >= 0.5f) { fB = true; vB = 0.f; }
        size_t base = ((size_t)(t * B_ + b) * C_ + rowq) * N_ + n0 + nA;
#pragma unroll
        for (int d = 0; d < 6; ++d) {
            __half h2[2];
            h2[0] = (fA && ((kbA[d] >> t) & 1u)) ? __float2half(1.0f) : __float2half(0.0f);
            h2[1] = (fB && ((kbB[d] >> t) & 1u)) ? __float2half(1.0f) : __float2half(0.0f);
            *(uint*)(y + base + (size_t)d * N_) = *(uint*)h2;
        }
    }
}

// ---------------- launch ---------------------------------------------------
extern "C" void kernel_launch(void* const* d_in, const int* in_sizes, int n_in,
                              void* d_out, int out_size)
{
    (void)in_sizes; (void)n_in; (void)out_size;
    const float* x       = (const float*)d_in[0];
    const float* q_w     = (const float*)d_in[1];
    const float* q_gamma = (const float*)d_in[2];
    const float* q_beta  = (const float*)d_in[3];
    const float* q_mean  = (const float*)d_in[4];
    const float* q_var   = (const float*)d_in[5];
    const float* k_w     = (const float*)d_in[6];
    const float* k_gamma = (const float*)d_in[7];
    const float* k_beta  = (const float*)d_in[8];
    const float* k_mean  = (const float*)d_in[9];
    const float* k_var   = (const float*)d_in[10];
    const float* proj_w  = (const float*)d_in[11];
    const float* proj_b  = (const float*)d_in[12];
    const float* proj_g  = (const float*)d_in[13];
    const float* proj_be = (const float*)d_in[14];
    const float* proj_m  = (const float*)d_in[15];
    const float* proj_v  = (const float*)d_in[16];
    const float* m_alpha = (const float*)d_in[17];
    float* out = (float*)d_out;

    __half *sT_p, *y_p, *wqk_hi, *wp_hi, *qk_p;
    float *bias_qk, *bias_p, *w32_p;
    cudaGetSymbolAddress((void**)&sT_p,    g_sT);
    cudaGetSymbolAddress((void**)&y_p,     g_y);
    cudaGetSymbolAddress((void**)&wqk_hi,  g_Wqk_hi);
    cudaGetSymbolAddress((void**)&w32_p,   g_Wqk_f32);
    cudaGetSymbolAddress((void**)&wp_hi,   g_Wp_hi);
    cudaGetSymbolAddress((void**)&qk_p,    g_qk);
    cudaGetSymbolAddress((void**)&bias_qk, g_bias_qk);
    cudaGetSymbolAddress((void**)&bias_p,  g_bias_p);

    cudaFuncSetAttribute((gemm_hi<true, true>),   cudaFuncAttributeMaxDynamicSharedMemorySize, GEMM_SMEM);
    cudaFuncSetAttribute((gemm_hi<false, false>), cudaFuncAttributeMaxDynamicSharedMemorySize, GEMM_SMEM);

    // K0: weight prep (BN fold; q/k hi + exact fp32; proj hi-only)
    prep_weights<<<(MQK * K_) / 256, 256>>>(q_w, q_gamma, q_beta, q_mean, q_var,
                                            k_w, k_gamma, k_beta, k_mean, k_var,
                                            proj_w, proj_b, proj_g, proj_be, proj_m, proj_v);
    // K1: LIF(x) -> sT ([z][n][c] only)
    lif_inputT<<<dim3(N_ / 32, C_ / 32, B_), 256>>>(x, sT_p);
    // K2: qk = [Wq';Wk']_hi @ sT^T + bias (col-major B; fp16 out; BK=64 pipelined)
    gemm_hi<true, true><<<dim3(N_ / BN, MQK / BM, T_ * B_), 256, GEMM_SMEM>>>(
        wqk_hi, sT_p, bias_qk, qk_p, MQK);
    // K3: approx spikes + exact threshold repair + attn gate -> y (R13 version)
    spike_attn2<<<B_ * HEADS_ * (N_ / 64), 256>>>(qk_p, m_alpha, sT_p, w32_p, bias_qk, y_p);
    // K4: out = Wp'_hi @ y + bias_p (row-major B; fp32 out; BK=64 pipelined)
    gemm_hi<false, false><<<dim3(N_ / BN, C_ / BM, T_ * B_), 256, GEMM_SMEM>>>(
        wp_hi, y_p, bias_p, out, C_);
}